// round 9
// baseline (speedup 1.0000x reference)
#include <cuda_runtime.h>

#define N    2048
#define DIM  1024
#define DCLI 64

// ---- device scratch (no allocations allowed) ----
__device__ float g_xim[N * DIM];          // normalized phi_im
__device__ float g_xcli[N * DCLI];        // normalized phi_cli
__device__ int g_idx[3][N];               // compacted original indices per class
__device__ int g_cnt[3];                  // class sizes
__device__ unsigned long long g_minkey[6];

// monotone order-preserving float<->uint encoding (ascending)
__device__ __forceinline__ unsigned int enc_f(float f) {
    unsigned int b = __float_as_uint(f);
    return (b & 0x80000000u) ? ~b : (b | 0x80000000u);
}
__device__ __forceinline__ float dec_f(unsigned int e) {
    unsigned int b = (e & 0x80000000u) ? (e ^ 0x80000000u) : ~e;
    return __uint_as_float(b);
}
__device__ __forceinline__ unsigned long long ullmin2(unsigned long long a, unsigned long long b) {
    return a < b ? a : b;
}

// ---- row L2 normalization ----
__global__ void norm_im(const float* __restrict__ x) {
    int row = blockIdx.x;
    int t = threadIdx.x;                          // 256 threads, 4 floats each
    float4 a = ((const float4*)(x + (size_t)row * DIM))[t];
    float ss = a.x * a.x + a.y * a.y + a.z * a.z + a.w * a.w;
    #pragma unroll
    for (int o = 16; o; o >>= 1) ss += __shfl_xor_sync(0xffffffffu, ss, o);
    __shared__ float sred[8];
    if ((t & 31) == 0) sred[t >> 5] = ss;
    __syncthreads();
    __shared__ float stot;
    if (t == 0) {
        float s = 0.f;
        #pragma unroll
        for (int w = 0; w < 8; w++) s += sred[w];
        stot = s;
    }
    __syncthreads();
    float inv = 1.0f / fmaxf(sqrtf(stot), 1e-12f);
    ((float4*)(g_xim + (size_t)row * DIM))[t] =
        make_float4(a.x * inv, a.y * inv, a.z * inv, a.w * inv);
}

__global__ void norm_cli(const float* __restrict__ x) {
    int row = blockIdx.x;
    int t = threadIdx.x;                          // 32 threads, 2 floats each
    float2 a = ((const float2*)(x + (size_t)row * DCLI))[t];
    float ss = a.x * a.x + a.y * a.y;
    #pragma unroll
    for (int o = 16; o; o >>= 1) ss += __shfl_xor_sync(0xffffffffu, ss, o);
    float inv = 1.0f / fmaxf(sqrtf(ss), 1e-12f);
    ((float2*)(g_xcli + (size_t)row * DCLI))[t] = make_float2(a.x * inv, a.y * inv);
}

// ---- dtype detect + mask build + deterministic compaction (one block) ----
__global__ void build_sets(const int* __restrict__ t32, const int* __restrict__ tr32) {
    const int t = threadIdx.x;
    const int lane = t & 31, warp = t >> 5;
    __shared__ int wsum[3][8];
    __shared__ int base[3];

    int nz = 0;
    for (int w = 2 * t + 1; w < 2 * N; w += 2 * 256)
        nz |= (t32[w] != 0);
    nz = __syncthreads_or(nz);
    const int i32 = nz;

    if (t < 3) base[t] = 0;
    if (t < 6) g_minkey[t] = 0xFF80000000000000ull;  // enc(+inf)<<32 | 0
    __syncthreads();

    for (int chunk = 0; chunk < N; chunk += 256) {
        int i = chunk + t;
        int t1, tr;
        if (i32) { t1 = t32[2 * i + 1]; tr = tr32[i]; }
        else     { t1 = t32[4 * i + 2]; tr = tr32[2 * i]; }  // low words (vals 0..2)
        bool mem[3];
        mem[0] = (t1 == 0) && (tr == 1);
        mem[1] = (t1 == 1);
        mem[2] = (t1 == 2);

        int wpre[3];
        #pragma unroll
        for (int c = 0; c < 3; c++) {
            unsigned b = __ballot_sync(0xffffffffu, mem[c]);
            wpre[c] = __popc(b & ((1u << lane) - 1u));
            if (lane == 0) wsum[c][warp] = __popc(b);
        }
        __syncthreads();
        int ctot[3];
        #pragma unroll
        for (int c = 0; c < 3; c++) {
            int woff = 0;
            #pragma unroll
            for (int w = 0; w < 8; w++) if (w < warp) woff += wsum[c][w];
            int tot = 0;
            #pragma unroll
            for (int w = 0; w < 8; w++) tot += wsum[c][w];
            if (mem[c]) g_idx[c][base[c] + woff + wpre[c]] = i;
            ctot[c] = tot;
        }
        __syncthreads();
        if (t == 0) {
            #pragma unroll
            for (int c = 0; c < 3; c++) base[c] += ctot[c];
        }
        __syncthreads();
    }
    if (t < 3) g_cnt[t] = base[t];
}

// ---- compacted pair-GEMM + scatter + min/argmin ----
// grid (32,32,6): z = modality*3 + pair. 64x64 tiles over compacted rectangles.
// 2-stage smem double buffer + register prefetch: one __syncthreads per K-step,
// LDG latency hidden under compute.
__global__ void __launch_bounds__(256) pairgemm(float* __restrict__ out) {
    const int z = blockIdx.z;
    const int mod = z / 3;          // 0: im (D=1024), 1: cli (D=64)
    const int p = z % 3;
    const int pa[3] = {0, 0, 1};
    const int pb[3] = {1, 2, 2};

    const int ca = g_cnt[pa[p]];
    const int cb = g_cnt[pb[p]];
    const int i0 = blockIdx.y * 64, j0 = blockIdx.x * 64;
    if (i0 >= ca || j0 >= cb) return;

    const int* __restrict__ idxA = g_idx[pa[p]];
    const int* __restrict__ idxB = g_idx[pb[p]];
    const float* __restrict__ Xn = (mod == 0) ? g_xim : g_xcli;
    const int D = (mod == 0) ? DIM : DCLI;

    __shared__ float As[2][16][64];
    __shared__ float Bs[2][16][64];
    __shared__ unsigned long long smk[8];

    const int t = threadIdx.x;
    const int lr = t >> 2;            // 0..63 row within tile to load
    const int ls = (t & 3) * 4;       // 0,4,8,12 k-segment
    const int tx = t & 15, ty = t >> 4;

    const int ga = idxA[min(i0 + lr, ca - 1)];
    const int gb = idxB[min(j0 + lr, cb - 1)];
    const float* Arow = Xn + (size_t)ga * D + ls;
    const float* Brow = Xn + (size_t)gb * D + ls;

    float acc[4][4];
    #pragma unroll
    for (int m = 0; m < 4; m++)
        #pragma unroll
        for (int n = 0; n < 4; n++) acc[m][n] = 0.f;

    // prologue: load stage 0
    {
        float4 a = *(const float4*)(Arow);
        float4 b = *(const float4*)(Brow);
        As[0][ls + 0][lr] = a.x; As[0][ls + 1][lr] = a.y; As[0][ls + 2][lr] = a.z; As[0][ls + 3][lr] = a.w;
        Bs[0][ls + 0][lr] = b.x; Bs[0][ls + 1][lr] = b.y; Bs[0][ls + 2][lr] = b.z; Bs[0][ls + 3][lr] = b.w;
    }
    __syncthreads();

    const int stages = D >> 4;
    for (int s = 0; s < stages; s++) {
        const int cur = s & 1, nxt = cur ^ 1;
        float4 na, nb;
        if (s + 1 < stages) {                 // prefetch next chunk (hidden under compute)
            na = *(const float4*)(Arow + (s + 1) * 16);
            nb = *(const float4*)(Brow + (s + 1) * 16);
        }
        #pragma unroll
        for (int kk = 0; kk < 16; kk++) {
            float4 ra = *(const float4*)&As[cur][kk][ty * 4];
            float4 rb = *(const float4*)&Bs[cur][kk][tx * 4];
            acc[0][0] += ra.x * rb.x; acc[0][1] += ra.x * rb.y; acc[0][2] += ra.x * rb.z; acc[0][3] += ra.x * rb.w;
            acc[1][0] += ra.y * rb.x; acc[1][1] += ra.y * rb.y; acc[1][2] += ra.y * rb.z; acc[1][3] += ra.y * rb.w;
            acc[2][0] += ra.z * rb.x; acc[2][1] += ra.z * rb.y; acc[2][2] += ra.z * rb.z; acc[2][3] += ra.z * rb.w;
            acc[3][0] += ra.w * rb.x; acc[3][1] += ra.w * rb.y; acc[3][2] += ra.w * rb.z; acc[3][3] += ra.w * rb.w;
        }
        if (s + 1 < stages) {                 // store into the other buffer (no WAR)
            As[nxt][ls + 0][lr] = na.x; As[nxt][ls + 1][lr] = na.y; As[nxt][ls + 2][lr] = na.z; As[nxt][ls + 3][lr] = na.w;
            Bs[nxt][ls + 0][lr] = nb.x; Bs[nxt][ls + 1][lr] = nb.y; Bs[nxt][ls + 2][lr] = nb.z; Bs[nxt][ls + 3][lr] = nb.w;
        }
        __syncthreads();                      // single barrier per K-step
    }

    // epilogue: scatter valid entries to original coordinates + min-key
    const int ib = i0 + ty * 4;
    const int jb = j0 + tx * 4;
    int gi[4], gj[4];
    #pragma unroll
    for (int m = 0; m < 4; m++) gi[m] = (ib + m < ca) ? idxA[ib + m] : -1;
    #pragma unroll
    for (int n = 0; n < 4; n++) gj[n] = (jb + n < cb) ? idxB[jb + n] : -1;

    float* __restrict__ po = out + (size_t)z * N * N;
    unsigned long long mk = 0xFFFFFFFFFFFFFFFFull;
    #pragma unroll
    for (int m = 0; m < 4; m++) {
        if (gi[m] < 0) continue;
        #pragma unroll
        for (int n = 0; n < 4; n++) {
            if (gj[n] < 0) continue;
            unsigned int off = (unsigned int)(gi[m] * N + gj[n]);
            po[off] = acc[m][n];
            unsigned long long key =
                ((unsigned long long)enc_f(acc[m][n]) << 32) | off;
            mk = ullmin2(mk, key);
        }
    }

    // warp shuffle min-reduce, then 8-way shared reduce, one atomic per block
    #pragma unroll
    for (int o = 16; o; o >>= 1) {
        unsigned long long other = __shfl_xor_sync(0xffffffffu, mk, o);
        mk = ullmin2(mk, other);
    }
    if ((t & 31) == 0) smk[t >> 5] = mk;
    __syncthreads();
    if (t == 0) {
        unsigned long long r = smk[0];
        #pragma unroll
        for (int w = 1; w < 8; w++) r = ullmin2(r, smk[w]);
        atomicMin(&g_minkey[z], r);
    }
}

// ---- finalize: decode keys into min_vals + min_idx (bounds-guarded) ----
__global__ void finalize(float* __restrict__ out, long long out_elems) {
    int i = threadIdx.x;
    if (i < 6) {
        unsigned long long k = g_minkey[i];
        float v = dec_f((unsigned int)(k >> 32));
        unsigned int flat = (unsigned int)(k & 0xFFFFFFFFull);
        long long base = (long long)6 * N * N;
        if (base + i < out_elems)
            out[base + i] = v;
        if (base + 6 + 2 * i + 1 < out_elems) {
            out[base + 6 + 2 * i]     = (float)(flat / N);
            out[base + 6 + 2 * i + 1] = (float)(flat % N);
        }
    }
}

extern "C" void kernel_launch(void* const* d_in, const int* in_sizes, int n_in,
                              void* d_out, int out_size) {
    const float* phi_im  = (const float*)d_in[0];
    const float* phi_cli = (const float*)d_in[1];
    const int*   t32     = (const int*)d_in[2];
    const int*   tr32    = (const int*)d_in[3];
    float* out = (float*)d_out;

    // background zeros for all 6 masked matrices (capturable memset node)
    cudaMemsetAsync(d_out, 0, (size_t)out_size * sizeof(float), 0);

    norm_im<<<N, 256>>>(phi_im);
    norm_cli<<<N, 32>>>(phi_cli);
    build_sets<<<1, 256>>>(t32, tr32);

    pairgemm<<<dim3(32, 32, 6), 256>>>(out);
    finalize<<<1, 32>>>(out, (long long)out_size);
}

// round 10
// speedup vs baseline: 1.4972x; 1.4972x over previous
#include <cuda_runtime.h>

#define N    2048
#define DIM  1024
#define DCLI 64
#define TCAP 288          // >= max tiles per pair: ceil(a/64)*ceil(b/64) <= 272 for a+b<=2048

// ---- device scratch (no allocations allowed) ----
__device__ float g_xim[N * DIM];          // normalized phi_im
__device__ float g_xcli[N * DCLI];        // normalized phi_cli
__device__ int g_idx[3][N];               // compacted original indices per class
__device__ int g_cnt[3];                  // class sizes
__device__ unsigned long long g_minkey[6];
__device__ float g_part[3 * 4 * TCAP * 4096];   // split-K partials (56.6 MB)

// monotone order-preserving float<->uint encoding (ascending)
__device__ __forceinline__ unsigned int enc_f(float f) {
    unsigned int b = __float_as_uint(f);
    return (b & 0x80000000u) ? ~b : (b | 0x80000000u);
}
__device__ __forceinline__ float dec_f(unsigned int e) {
    unsigned int b = (e & 0x80000000u) ? (e ^ 0x80000000u) : ~e;
    return __uint_as_float(b);
}
__device__ __forceinline__ unsigned long long ullmin2(unsigned long long a, unsigned long long b) {
    return a < b ? a : b;
}

// ---- row L2 normalization ----
__global__ void norm_im(const float* __restrict__ x) {
    int row = blockIdx.x;
    int t = threadIdx.x;                          // 256 threads, 4 floats each
    float4 a = ((const float4*)(x + (size_t)row * DIM))[t];
    float ss = a.x * a.x + a.y * a.y + a.z * a.z + a.w * a.w;
    #pragma unroll
    for (int o = 16; o; o >>= 1) ss += __shfl_xor_sync(0xffffffffu, ss, o);
    __shared__ float sred[8];
    if ((t & 31) == 0) sred[t >> 5] = ss;
    __syncthreads();
    __shared__ float stot;
    if (t == 0) {
        float s = 0.f;
        #pragma unroll
        for (int w = 0; w < 8; w++) s += sred[w];
        stot = s;
    }
    __syncthreads();
    float inv = 1.0f / fmaxf(sqrtf(stot), 1e-12f);
    ((float4*)(g_xim + (size_t)row * DIM))[t] =
        make_float4(a.x * inv, a.y * inv, a.z * inv, a.w * inv);
}

__global__ void norm_cli(const float* __restrict__ x) {
    int row = blockIdx.x;
    int t = threadIdx.x;                          // 32 threads, 2 floats each
    float2 a = ((const float2*)(x + (size_t)row * DCLI))[t];
    float ss = a.x * a.x + a.y * a.y;
    #pragma unroll
    for (int o = 16; o; o >>= 1) ss += __shfl_xor_sync(0xffffffffu, ss, o);
    float inv = 1.0f / fmaxf(sqrtf(ss), 1e-12f);
    ((float2*)(g_xcli + (size_t)row * DCLI))[t] = make_float2(a.x * inv, a.y * inv);
}

// ---- dtype detect + mask build + deterministic compaction (one block) ----
__global__ void build_sets(const int* __restrict__ t32, const int* __restrict__ tr32) {
    const int t = threadIdx.x;
    const int lane = t & 31, warp = t >> 5;
    __shared__ int wsum[3][8];
    __shared__ int base[3];

    int nz = 0;
    for (int w = 2 * t + 1; w < 2 * N; w += 2 * 256)
        nz |= (t32[w] != 0);
    nz = __syncthreads_or(nz);
    const int i32 = nz;

    if (t < 3) base[t] = 0;
    if (t < 6) g_minkey[t] = 0xFF80000000000000ull;  // enc(+inf)<<32 | 0
    __syncthreads();

    for (int chunk = 0; chunk < N; chunk += 256) {
        int i = chunk + t;
        int t1, tr;
        if (i32) { t1 = t32[2 * i + 1]; tr = tr32[i]; }
        else     { t1 = t32[4 * i + 2]; tr = tr32[2 * i]; }  // low words (vals 0..2)
        bool mem[3];
        mem[0] = (t1 == 0) && (tr == 1);
        mem[1] = (t1 == 1);
        mem[2] = (t1 == 2);

        int wpre[3];
        #pragma unroll
        for (int c = 0; c < 3; c++) {
            unsigned b = __ballot_sync(0xffffffffu, mem[c]);
            wpre[c] = __popc(b & ((1u << lane) - 1u));
            if (lane == 0) wsum[c][warp] = __popc(b);
        }
        __syncthreads();
        int ctot[3];
        #pragma unroll
        for (int c = 0; c < 3; c++) {
            int woff = 0;
            #pragma unroll
            for (int w = 0; w < 8; w++) if (w < warp) woff += wsum[c][w];
            int tot = 0;
            #pragma unroll
            for (int w = 0; w < 8; w++) tot += wsum[c][w];
            if (mem[c]) g_idx[c][base[c] + woff + wpre[c]] = i;
            ctot[c] = tot;
        }
        __syncthreads();
        if (t == 0) {
            #pragma unroll
            for (int c = 0; c < 3; c++) base[c] += ctot[c];
        }
        __syncthreads();
    }
    if (t < 3) g_cnt[t] = base[t];
}

// ---- compacted pair-GEMM, split-K over the D=1024 modality ----
// grid (32,32,15): z<12 -> mod0, pair=z>>2, split=z&3, K chunk of 256 -> partials;
//                  z>=12 -> mod1 (D=64), direct scatter + min epilogue.
__global__ void __launch_bounds__(256, 4) pairgemm(float* __restrict__ out) {
    const int z = blockIdx.z;
    const int mod   = (z < 12) ? 0 : 1;
    const int p     = (z < 12) ? (z >> 2) : (z - 12);
    const int split = (z < 12) ? (z & 3) : 0;
    const int pa[3] = {0, 0, 1};
    const int pb[3] = {1, 2, 2};

    const int ca = g_cnt[pa[p]];
    const int cb = g_cnt[pb[p]];
    const int i0 = blockIdx.y * 64, j0 = blockIdx.x * 64;
    if (i0 >= ca || j0 >= cb) return;

    const int* __restrict__ idxA = g_idx[pa[p]];
    const int* __restrict__ idxB = g_idx[pb[p]];
    const float* __restrict__ Xn = (mod == 0) ? g_xim : g_xcli;
    const int D    = (mod == 0) ? DIM : DCLI;
    const int kbeg = (mod == 0) ? split * 256 : 0;
    const int stages = (mod == 0) ? 16 : 4;     // 16-wide K steps

    __shared__ float As[2][16][64];
    __shared__ float Bs[2][16][64];
    __shared__ unsigned long long smk[8];

    const int t = threadIdx.x;
    const int lr = t >> 2;            // 0..63 row within tile to load
    const int ls = (t & 3) * 4;       // 0,4,8,12 k-segment
    const int tx = t & 15, ty = t >> 4;

    const int ga = idxA[min(i0 + lr, ca - 1)];
    const int gb = idxB[min(j0 + lr, cb - 1)];
    const float* Arow = Xn + (size_t)ga * D + kbeg + ls;
    const float* Brow = Xn + (size_t)gb * D + kbeg + ls;

    float acc[4][4];
    #pragma unroll
    for (int m = 0; m < 4; m++)
        #pragma unroll
        for (int n = 0; n < 4; n++) acc[m][n] = 0.f;

    {   // prologue: stage 0
        float4 a = *(const float4*)(Arow);
        float4 b = *(const float4*)(Brow);
        As[0][ls + 0][lr] = a.x; As[0][ls + 1][lr] = a.y; As[0][ls + 2][lr] = a.z; As[0][ls + 3][lr] = a.w;
        Bs[0][ls + 0][lr] = b.x; Bs[0][ls + 1][lr] = b.y; Bs[0][ls + 2][lr] = b.z; Bs[0][ls + 3][lr] = b.w;
    }
    __syncthreads();

    for (int s = 0; s < stages; s++) {
        const int cur = s & 1, nxt = cur ^ 1;
        float4 na, nb;
        if (s + 1 < stages) {
            na = *(const float4*)(Arow + (s + 1) * 16);
            nb = *(const float4*)(Brow + (s + 1) * 16);
        }
        #pragma unroll
        for (int kk = 0; kk < 16; kk++) {
            float4 ra = *(const float4*)&As[cur][kk][ty * 4];
            float4 rb = *(const float4*)&Bs[cur][kk][tx * 4];
            acc[0][0] += ra.x * rb.x; acc[0][1] += ra.x * rb.y; acc[0][2] += ra.x * rb.z; acc[0][3] += ra.x * rb.w;
            acc[1][0] += ra.y * rb.x; acc[1][1] += ra.y * rb.y; acc[1][2] += ra.y * rb.z; acc[1][3] += ra.y * rb.w;
            acc[2][0] += ra.z * rb.x; acc[2][1] += ra.z * rb.y; acc[2][2] += ra.z * rb.z; acc[2][3] += ra.z * rb.w;
            acc[3][0] += ra.w * rb.x; acc[3][1] += ra.w * rb.y; acc[3][2] += ra.w * rb.z; acc[3][3] += ra.w * rb.w;
        }
        if (s + 1 < stages) {
            As[nxt][ls + 0][lr] = na.x; As[nxt][ls + 1][lr] = na.y; As[nxt][ls + 2][lr] = na.z; As[nxt][ls + 3][lr] = na.w;
            Bs[nxt][ls + 0][lr] = nb.x; Bs[nxt][ls + 1][lr] = nb.y; Bs[nxt][ls + 2][lr] = nb.z; Bs[nxt][ls + 3][lr] = nb.w;
        }
        __syncthreads();
    }

    if (mod == 0) {
        // write 64x64 partial tile to scratch (compact tile indexing)
        const int ntx = (cb + 63) >> 6;
        float* pp = g_part +
            ((size_t)(p * 4 + split) * TCAP + (size_t)blockIdx.y * ntx + blockIdx.x) * 4096;
        #pragma unroll
        for (int m = 0; m < 4; m++)
            *(float4*)(pp + (ty * 4 + m) * 64 + tx * 4) =
                make_float4(acc[m][0], acc[m][1], acc[m][2], acc[m][3]);
        return;
    }

    // mod1: direct scatter + min epilogue
    const int ib = i0 + ty * 4;
    const int jb = j0 + tx * 4;
    int gi[4], gj[4];
    #pragma unroll
    for (int m = 0; m < 4; m++) gi[m] = (ib + m < ca) ? idxA[ib + m] : -1;
    #pragma unroll
    for (int n = 0; n < 4; n++) gj[n] = (jb + n < cb) ? idxB[jb + n] : -1;

    float* __restrict__ po = out + (size_t)(3 + p) * N * N;
    unsigned long long mk = 0xFFFFFFFFFFFFFFFFull;
    #pragma unroll
    for (int m = 0; m < 4; m++) {
        if (gi[m] < 0) continue;
        #pragma unroll
        for (int n = 0; n < 4; n++) {
            if (gj[n] < 0) continue;
            unsigned int off = (unsigned int)(gi[m] * N + gj[n]);
            po[off] = acc[m][n];
            mk = ullmin2(mk, ((unsigned long long)enc_f(acc[m][n]) << 32) | off);
        }
    }
    #pragma unroll
    for (int o = 16; o; o >>= 1)
        mk = ullmin2(mk, __shfl_xor_sync(0xffffffffu, mk, o));
    if ((t & 31) == 0) smk[t >> 5] = mk;
    __syncthreads();
    if (t == 0) {
        unsigned long long r = smk[0];
        #pragma unroll
        for (int w = 1; w < 8; w++) r = ullmin2(r, smk[w]);
        atomicMin(&g_minkey[3 + p], r);
    }
}

// ---- combine split-K partials: fixed-order sum + scatter + min (mod0) ----
__global__ void __launch_bounds__(256) combine(float* __restrict__ out) {
    const int p = blockIdx.z;
    const int pa[3] = {0, 0, 1};
    const int pb[3] = {1, 2, 2};
    const int ca = g_cnt[pa[p]];
    const int cb = g_cnt[pb[p]];
    const int i0 = blockIdx.y * 64, j0 = blockIdx.x * 64;
    if (i0 >= ca || j0 >= cb) return;

    const int ntx = (cb + 63) >> 6;
    const size_t slot = (size_t)blockIdx.y * ntx + blockIdx.x;
    const float4* P0 = (const float4*)(g_part + ((size_t)(p * 4 + 0) * TCAP + slot) * 4096);
    const float4* P1 = (const float4*)(g_part + ((size_t)(p * 4 + 1) * TCAP + slot) * 4096);
    const float4* P2 = (const float4*)(g_part + ((size_t)(p * 4 + 2) * TCAP + slot) * 4096);
    const float4* P3 = (const float4*)(g_part + ((size_t)(p * 4 + 3) * TCAP + slot) * 4096);

    const int* __restrict__ idxA = g_idx[pa[p]];
    const int* __restrict__ idxB = g_idx[pb[p]];
    float* __restrict__ po = out + (size_t)p * N * N;

    __shared__ unsigned long long smk[8];
    const int t = threadIdx.x;
    unsigned long long mk = 0xFFFFFFFFFFFFFFFFull;

    #pragma unroll
    for (int r = 0; r < 4; r++) {
        int f4 = t + r * 256;                 // 0..1023 float4 within 64x64 tile
        float4 v = P0[f4];
        float4 b1 = P1[f4]; v.x += b1.x; v.y += b1.y; v.z += b1.z; v.w += b1.w;
        float4 b2 = P2[f4]; v.x += b2.x; v.y += b2.y; v.z += b2.z; v.w += b2.w;
        float4 b3 = P3[f4]; v.x += b3.x; v.y += b3.y; v.z += b3.z; v.w += b3.w;
        int e = f4 * 4;
        int row = e >> 6, col = e & 63;
        if (i0 + row >= ca) continue;
        int gi = idxA[i0 + row];
        float vv[4] = {v.x, v.y, v.z, v.w};
        #pragma unroll
        for (int c = 0; c < 4; c++) {
            int jj = j0 + col + c;
            if (jj >= cb) continue;
            unsigned int off = (unsigned int)(gi * N + idxB[jj]);
            po[off] = vv[c];
            mk = ullmin2(mk, ((unsigned long long)enc_f(vv[c]) << 32) | off);
        }
    }

    #pragma unroll
    for (int o = 16; o; o >>= 1)
        mk = ullmin2(mk, __shfl_xor_sync(0xffffffffu, mk, o));
    if ((t & 31) == 0) smk[t >> 5] = mk;
    __syncthreads();
    if (t == 0) {
        unsigned long long r = smk[0];
        #pragma unroll
        for (int w = 1; w < 8; w++) r = ullmin2(r, smk[w]);
        atomicMin(&g_minkey[p], r);
    }
}

// ---- finalize: decode keys into min_vals + min_idx (bounds-guarded) ----
__global__ void finalize(float* __restrict__ out, long long out_elems) {
    int i = threadIdx.x;
    if (i < 6) {
        unsigned long long k = g_minkey[i];
        float v = dec_f((unsigned int)(k >> 32));
        unsigned int flat = (unsigned int)(k & 0xFFFFFFFFull);
        long long base = (long long)6 * N * N;
        if (base + i < out_elems)
            out[base + i] = v;
        if (base + 6 + 2 * i + 1 < out_elems) {
            out[base + 6 + 2 * i]     = (float)(flat / N);
            out[base + 6 + 2 * i + 1] = (float)(flat % N);
        }
    }
}

extern "C" void kernel_launch(void* const* d_in, const int* in_sizes, int n_in,
                              void* d_out, int out_size) {
    const float* phi_im  = (const float*)d_in[0];
    const float* phi_cli = (const float*)d_in[1];
    const int*   t32     = (const int*)d_in[2];
    const int*   tr32    = (const int*)d_in[3];
    float* out = (float*)d_out;

    // background zeros for all 6 masked matrices (capturable memset node)
    cudaMemsetAsync(d_out, 0, (size_t)out_size * sizeof(float), 0);

    norm_im<<<N, 256>>>(phi_im);
    norm_cli<<<N, 32>>>(phi_cli);
    build_sets<<<1, 256>>>(t32, tr32);

    pairgemm<<<dim3(32, 32, 15), 256>>>(out);
    combine<<<dim3(32, 32, 3), 256>>>(out);
    finalize<<<1, 32>>>(out, (long long)out_size);
}